// round 14
// baseline (speedup 1.0000x reference)
#include <cuda_runtime.h>
#include <cuda_fp16.h>
#include <cstdint>

#define N_TOK 32768
#define DIMX  1024
#define HID   2816
#define BK    64                    // halves per k-tile (128B data per row)
#define STAGES 3
#define ROWPITCH 144                // 128B data + 16B pad -> conflict-free ldmatrix
#define A_BYTES (128 * ROWPITCH)    // 18432
#define STAGE_BYTES (2 * A_BYTES)   // A(128 rows) + B(128 rows) = 36864
#define DYN_SMEM (STAGES * STAGE_BYTES)   // 110592

// ---------------- device scratch (no allocations allowed) -------------------
__device__ int    g_count[2];                        // zeroed by detect_kernel
__device__ int    g_slot[N_TOK];                     // token -> slot
__device__ int    g_word_mode = 1;                   // re-armed by rms_scatter
__device__ __half g_xh[(size_t)2 * N_TOK * DIMX];    // gathered x, fp16
__device__ __half g_h [(size_t)2 * N_TOK * HID];     // silu(xW1^T)*(xW3^T), fp16
__device__ __half g_o [(size_t)2 * N_TOK * DIMX];    // h W2^T, fp16
__device__ __half g_w1h[(size_t)2 * HID * DIMX];
__device__ __half g_w3h[(size_t)2 * HID * DIMX];
__device__ __half g_w2h[(size_t)2 * DIMX * HID];

// ---------------- PTX helpers ------------------------------------------------
__device__ __forceinline__ uint32_t smem_u32(const void* p) {
    uint32_t a;
    asm("{ .reg .u64 t; cvta.to.shared.u64 t, %1; cvt.u32.u64 %0, t; }" : "=r"(a) : "l"(p));
    return a;
}
__device__ __forceinline__ void cp16s(uint32_t dst, const void* src) {
    asm volatile("cp.async.cg.shared.global [%0], [%1], 16;" :: "r"(dst), "l"(src));
}
__device__ __forceinline__ void ldmx4(uint32_t* r, uint32_t addr) {
    asm volatile("ldmatrix.sync.aligned.m8n8.x4.shared.b16 {%0,%1,%2,%3}, [%4];"
                 : "=r"(r[0]), "=r"(r[1]), "=r"(r[2]), "=r"(r[3]) : "r"(addr));
}
__device__ __forceinline__ void mma16816(float* c, const uint32_t* a, const uint32_t* b) {
    asm volatile(
        "mma.sync.aligned.m16n8k16.row.col.f32.f16.f16.f32 "
        "{%0,%1,%2,%3}, {%4,%5,%6,%7}, {%8,%9}, {%0,%1,%2,%3};"
        : "+f"(c[0]), "+f"(c[1]), "+f"(c[2]), "+f"(c[3])
        : "r"(a[0]), "r"(a[1]), "r"(a[2]), "r"(a[3]), "r"(b[0]), "r"(b[1]));
}
__device__ __forceinline__ float silu_f(float x) { return x / (1.0f + __expf(-x)); }

// ---------------- small kernels ----------------------------------------------
__global__ void detect_kernel(const unsigned int* __restrict__ m) {
    int i = blockIdx.x * blockDim.x + threadIdx.x;   // 16384 threads = 64KB, in-bounds either way
    if (i == 0) { g_count[0] = 0; g_count[1] = 0; }
    unsigned v = m[i];
    if (v != 0u && v != 1u && v != 0x3F800000u) g_word_mode = 0;
}
__global__ void route_gather(const void* __restrict__ masks, const float* __restrict__ x) {
    int t = blockIdx.x;
    __shared__ int s_slot;
    if (threadIdx.x == 0) {
        bool m0;
        if (g_word_mode) m0 = ((const unsigned int*)masks)[t] != 0u;
        else             m0 = ((const unsigned char*)masks)[t] != 0;
        int e = m0 ? 0 : 1;                    // modality 0 wins on overlap
        int s = atomicAdd(&g_count[e], 1);
        int slot = e * N_TOK + s;
        g_slot[t] = slot;
        s_slot = slot;
    }
    __syncthreads();
    int slot = s_slot;
    float4 v = ((const float4*)(x + (size_t)t * DIMX))[threadIdx.x];
    __half2 h0 = __floats2half2_rn(v.x, v.y);
    __half2 h1 = __floats2half2_rn(v.z, v.w);
    ((uint2*)(g_xh + (size_t)slot * DIMX))[threadIdx.x] =
        make_uint2(*(uint32_t*)&h0, *(uint32_t*)&h1);
}
// convert all three weight tensors; 8 floats per iteration (uint4 store)
__global__ void cvtw_all(const float4* __restrict__ w1, const float4* __restrict__ w3,
                         const float4* __restrict__ w2,
                         uint4* __restrict__ d1, uint4* __restrict__ d3,
                         uint4* __restrict__ d2, int n8) {
    int stride = gridDim.x * blockDim.x;
    for (int i = blockIdx.x * blockDim.x + threadIdx.x; i < 3 * n8; i += stride) {
        const float4* s; uint4* d; int j;
        if (i < n8)          { s = w1; d = d1; j = i; }
        else if (i < 2 * n8) { s = w3; d = d3; j = i - n8; }
        else                 { s = w2; d = d2; j = i - 2 * n8; }
        float4 va = s[2 * j], vb = s[2 * j + 1];
        __half2 h0 = __floats2half2_rn(va.x, va.y);
        __half2 h1 = __floats2half2_rn(va.z, va.w);
        __half2 h2 = __floats2half2_rn(vb.x, vb.y);
        __half2 h3 = __floats2half2_rn(vb.z, vb.w);
        d[j] = make_uint4(*(uint32_t*)&h0, *(uint32_t*)&h1,
                          *(uint32_t*)&h2, *(uint32_t*)&h3);
    }
}

// ---------------- fp16 tensor-core GEMM, 512 threads / 32-reg acc -------------
// CTA tile 128x128, 16 warps: wr = wid&3 over M (32 rows), wc = wid>>2 over N.
// Warp tile 32 rows x 32 cols -> acc 32 regs/thread -> 2 CTAs/SM = 32 warps/SM.
// DUAL : B = [w1 (64 rows) | w3 (64 rows)]; warp covers 16 w1-cols + 16 w3-cols;
//        epilogue silu(d1)*d3 -> fp16 C.   NTILE = 64.
// !DUAL: B = 128-row weight tile; warp covers 32 cols; fp16 C.  NTILE = 128.
// Pipeline: 3 stages x BK=64, ONE __syncthreads per k-tile.
template <bool DUAL, int K, int NC, int NTILE>
__global__ void __launch_bounds__(512, 2)
gemm_fp16(const __half* __restrict__ A,
          const __half* __restrict__ W1,
          const __half* __restrict__ W3,
          void* __restrict__ Cout)
{
    extern __shared__ char dyn[];
    const int tid = threadIdx.x;
    const int wid = tid >> 5;
    const int l   = tid & 31;
    const int r0  = blockIdx.y * 128;
    const int e   = r0 >> 15;
    if ((r0 & (N_TOK - 1)) >= g_count[e]) return;
    const int cb  = blockIdx.x * NTILE;

    const uint32_t smem = smem_u32(dyn);
    const __half* W1e = W1 + (size_t)e * NC * K;
    const __half* W3e = DUAL ? (W3 + (size_t)e * NC * K) : W1e;

    // ---- compact loader: 4 chunks/thread (A rows tr,tr+64; B rows tr,tr+64) --
    const int tr = tid >> 3, tc = tid & 7;            // tr in 0..63
    const __half* aSrc  = A + (size_t)(r0 + tr) * K + tc * 8;
    const __half* b1Src = W1e + (size_t)(cb + tr) * K + tc * 8;          // B rows 0-63
    const __half* b3Src = DUAL ? (W3e + (size_t)(cb + tr) * K + tc * 8)  // B rows 64-127
                               : (W1e + (size_t)(cb + 64 + tr) * K + tc * 8);
    const uint32_t offA = tr * ROWPITCH + tc * 16;
    const uint32_t offB = A_BYTES + offA;

    // ---- ldmatrix lane offsets ----
    const int wr = wid & 3, wc = wid >> 2;            // wc in 0..3
    uint32_t a_off[2];
#pragma unroll
    for (int mi = 0; mi < 2; mi++)
        a_off[mi] = (wr * 32 + mi * 16 + (l & 15)) * ROWPITCH + (l >> 4) * 16;
    // bx = first 16-col group, by = second
    const uint32_t bgrp = (l & 7) + ((l >> 4) << 3);
    uint32_t bx_off, by_off;
    if (DUAL) {
        bx_off = A_BYTES + (wc * 16 + bgrp) * ROWPITCH + ((l >> 3) & 1) * 16;
        by_off = bx_off + 64 * ROWPITCH;              // matching w3 cols
    } else {
        bx_off = A_BYTES + (wc * 32 + bgrp) * ROWPITCH + ((l >> 3) & 1) * 16;
        by_off = bx_off + 16 * ROWPITCH;              // cols +16..+31
    }

    float acc[2][4][4];                               // 32 regs
#pragma unroll
    for (int mi = 0; mi < 2; mi++)
#pragma unroll
        for (int ni = 0; ni < 4; ni++)
#pragma unroll
            for (int q = 0; q < 4; q++) acc[mi][ni][q] = 0.f;

    const int KT = K / BK;
    // prologue: fill STAGES-1 stages
#pragma unroll
    for (int s = 0; s < STAGES - 1; s++) {
        const uint32_t sb = smem + s * STAGE_BYTES;
        const int k0 = s * BK;
        cp16s(sb + offA,                  aSrc + k0);
        cp16s(sb + offA + 64 * ROWPITCH,  aSrc + (size_t)64 * K + k0);
        cp16s(sb + offB,                  b1Src + k0);
        cp16s(sb + offB + 64 * ROWPITCH,  b3Src + k0);
        asm volatile("cp.async.commit_group;");
    }

    for (int kt = 0; kt < KT; kt++) {
        asm volatile("cp.async.wait_group %0;" :: "n"(STAGES - 2));
        __syncthreads();

        if (kt + STAGES - 1 < KT) {
            const uint32_t dst = smem + ((kt + STAGES - 1) % STAGES) * STAGE_BYTES;
            const int k0 = (kt + STAGES - 1) * BK;
            cp16s(dst + offA,                  aSrc + k0);
            cp16s(dst + offA + 64 * ROWPITCH,  aSrc + (size_t)64 * K + k0);
            cp16s(dst + offB,                  b1Src + k0);
            cp16s(dst + offB + 64 * ROWPITCH,  b3Src + k0);
        }
        asm volatile("cp.async.commit_group;");   // uniform group count

        const uint32_t st = smem + (kt % STAGES) * STAGE_BYTES;
#pragma unroll
        for (int kk = 0; kk < 4; kk++) {
            uint32_t a[2][4], bx[4], by[4];
            ldmx4(a[0], st + a_off[0] + kk * 32);
            ldmx4(a[1], st + a_off[1] + kk * 32);
            ldmx4(bx,   st + bx_off   + kk * 32);
            ldmx4(by,   st + by_off   + kk * 32);
            // half-round 1: acc[.][0..1] with bx
#pragma unroll
            for (int ni = 0; ni < 2; ni++) {
                const uint32_t* f = &bx[ni * 2];
                mma16816(acc[0][ni], a[0], f);
                mma16816(acc[1][ni], a[1], f);
            }
            // half-round 2: acc[.][2..3] with by
#pragma unroll
            for (int ni = 0; ni < 2; ni++) {
                const uint32_t* f = &by[ni * 2];
                mma16816(acc[0][ni + 2], a[0], f);
                mma16816(acc[1][ni + 2], a[1], f);
            }
        }
    }

    // ---- epilogue (fp16) ----
    const int tgrp = l >> 2, tq = l & 3;
    __half* Ch = (__half*)Cout;
    if (DUAL) {
        // acc[.][0..1] = w1 cols (wc*16 + ni*8), acc[.][2..3] = matching w3 cols
#pragma unroll
        for (int mi = 0; mi < 2; mi++) {
            int row0 = r0 + wr * 32 + mi * 16 + tgrp;
#pragma unroll
            for (int ni = 0; ni < 2; ni++) {
                int col = cb + wc * 16 + ni * 8 + 2 * tq;
                float v0 = silu_f(acc[mi][ni][0]) * acc[mi][ni + 2][0];
                float v1 = silu_f(acc[mi][ni][1]) * acc[mi][ni + 2][1];
                float v2 = silu_f(acc[mi][ni][2]) * acc[mi][ni + 2][2];
                float v3 = silu_f(acc[mi][ni][3]) * acc[mi][ni + 2][3];
                *(__half2*)(Ch + (size_t)row0 * NC + col)       = __floats2half2_rn(v0, v1);
                *(__half2*)(Ch + (size_t)(row0 + 8) * NC + col) = __floats2half2_rn(v2, v3);
            }
        }
    } else {
        // acc[.][ni] = cols wc*32 + ni*8 (bx: 0,8; by: 16,24)
#pragma unroll
        for (int mi = 0; mi < 2; mi++) {
            int row0 = r0 + wr * 32 + mi * 16 + tgrp;
#pragma unroll
            for (int ni = 0; ni < 4; ni++) {
                int col = cb + wc * 32 + ni * 8 + 2 * tq;
                *(__half2*)(Ch + (size_t)row0 * NC + col) =
                    __floats2half2_rn(acc[mi][ni][0], acc[mi][ni][1]);
                *(__half2*)(Ch + (size_t)(row0 + 8) * NC + col) =
                    __floats2half2_rn(acc[mi][ni][2], acc[mi][ni][3]);
            }
        }
    }
}

// ---------------- RMSNorm + scale + scatter (2 tokens per 256-thr block) ------
__global__ void rms_scatter(const __half* __restrict__ o,
                            const float* __restrict__ norm_w,
                            float* __restrict__ out)
{
    int tid  = threadIdx.x;            // 256 threads: two 128-thread halves
    int half = tid >> 7;               // 0 or 1
    int lt   = tid & 127;
    int t    = blockIdx.x * 2 + half;
    if (t == 0 && lt == 0) g_word_mode = 1;   // re-arm for next call's detect
    int slot = g_slot[t];
    int e = slot >> 15;

    // 1024 halves per row = 128 uint4; one uint4 (8 halves) per thread
    uint4 d = ((const uint4*)(o + (size_t)slot * DIMX))[lt];
    float2 f0 = __half22float2(*(__half2*)&d.x);
    float2 f1 = __half22float2(*(__half2*)&d.y);
    float2 f2 = __half22float2(*(__half2*)&d.z);
    float2 f3 = __half22float2(*(__half2*)&d.w);
    float ss = f0.x*f0.x + f0.y*f0.y + f1.x*f1.x + f1.y*f1.y
             + f2.x*f2.x + f2.y*f2.y + f3.x*f3.x + f3.y*f3.y;
#pragma unroll
    for (int ofs = 16; ofs; ofs >>= 1) ss += __shfl_xor_sync(0xffffffffu, ss, ofs);
    __shared__ float wss[8];
    if ((tid & 31) == 0) wss[tid >> 5] = ss;
    __syncthreads();
    float r = rsqrtf((wss[half * 4] + wss[half * 4 + 1] +
                      wss[half * 4 + 2] + wss[half * 4 + 3]) * (1.0f / DIMX) + 1e-5f);

    const float4* g = (const float4*)(norm_w + (size_t)e * DIMX);
    float4 g0 = g[2 * lt], g1 = g[2 * lt + 1];
    float4* dst = (float4*)(out + (size_t)t * DIMX);
    dst[2 * lt]     = make_float4(f0.x*r*g0.x, f0.y*r*g0.y, f1.x*r*g0.z, f1.y*r*g0.w);
    dst[2 * lt + 1] = make_float4(f2.x*r*g1.x, f2.y*r*g1.y, f3.x*r*g1.z, f3.y*r*g1.w);
}

// ---------------- launcher ----------------------------------------------------
extern "C" void kernel_launch(void* const* d_in, const int* in_sizes, int n_in,
                              void* d_out, int out_size)
{
    const float* x     = (const float*)d_in[0];
    const void*  masks = d_in[1];
    const float* w1    = (const float*)d_in[2];
    const float* w3    = (const float*)d_in[3];
    const float* w2    = (const float*)d_in[4];
    const float* nw    = (const float*)d_in[5];
    float* out = (float*)d_out;

    cudaFuncSetAttribute(gemm_fp16<true,  DIMX, HID,  64>,
                         cudaFuncAttributeMaxDynamicSharedMemorySize, DYN_SMEM);
    cudaFuncSetAttribute(gemm_fp16<false, HID,  DIMX, 128>,
                         cudaFuncAttributeMaxDynamicSharedMemorySize, DYN_SMEM);

    void *xh, *hp, *op, *w1h, *w3h, *w2h;
    cudaGetSymbolAddress(&xh,  g_xh);
    cudaGetSymbolAddress(&hp,  g_h);
    cudaGetSymbolAddress(&op,  g_o);
    cudaGetSymbolAddress(&w1h, g_w1h);
    cudaGetSymbolAddress(&w3h, g_w3h);
    cudaGetSymbolAddress(&w2h, g_w2h);

    detect_kernel<<<64, 256>>>((const unsigned int*)masks);            // 0
    route_gather<<<N_TOK, 256>>>(masks, x);                            // 1

    const int n8 = 2 * HID * DIMX / 8;
    cvtw_all<<<1024, 256>>>((const float4*)w1, (const float4*)w3, (const float4*)w2,
                            (uint4*)w1h, (uint4*)w3h, (uint4*)w2h, n8);        // 2

    // GEMM1: [2N,1024] x w1/w3 -> fused SwiGLU -> g_h [2N, HID] fp16          // 3
    gemm_fp16<true, DIMX, HID, 64><<<dim3(HID / 64, 2 * N_TOK / 128), 512, DYN_SMEM>>>(
        (const __half*)xh, (const __half*)w1h, (const __half*)w3h, hp);
    // GEMM2: [2N,2816] x w2 -> g_o [2N, DIM] fp16                             // 4
    gemm_fp16<false, HID, DIMX, 128><<<dim3(DIMX / 128, 2 * N_TOK / 128), 512, DYN_SMEM>>>(
        (const __half*)hp, (const __half*)w2h, (const __half*)w2h, op);

    rms_scatter<<<N_TOK / 2, 256>>>((const __half*)op, nw, out);               // 5
}

// round 15
// speedup vs baseline: 1.0545x; 1.0545x over previous
#include <cuda_runtime.h>
#include <cuda_fp16.h>
#include <cstdint>

#define N_TOK 32768
#define DIMX  1024
#define HID   2816
#define BK    64                    // halves per k-tile (128B data per row)
#define STAGES 3
#define ROWPITCH 144                // 128B data + 16B pad -> conflict-free ldmatrix
#define A_BYTES (128 * ROWPITCH)    // 18432
#define STAGE_BYTES (2 * A_BYTES)   // A(128 rows) + B(128 rows) = 36864
#define DYN_SMEM (STAGES * STAGE_BYTES)   // 110592

// ---------------- device scratch (no allocations allowed) -------------------
__device__ int    g_count[2];                        // zeroed by detect_kernel
__device__ int    g_slot[N_TOK];                     // token -> slot
__device__ int    g_word_mode = 1;                   // re-armed by rms_scatter
__device__ __half g_xh[(size_t)2 * N_TOK * DIMX];    // gathered x, fp16
__device__ __half g_h [(size_t)2 * N_TOK * HID];     // silu(xW1^T)*(xW3^T), fp16
__device__ __half g_o [(size_t)2 * N_TOK * DIMX];    // h W2^T, fp16
__device__ __half g_w1h[(size_t)2 * HID * DIMX];
__device__ __half g_w3h[(size_t)2 * HID * DIMX];
__device__ __half g_w2h[(size_t)2 * DIMX * HID];

// ---------------- PTX helpers ------------------------------------------------
__device__ __forceinline__ uint32_t smem_u32(const void* p) {
    uint32_t a;
    asm("{ .reg .u64 t; cvta.to.shared.u64 t, %1; cvt.u32.u64 %0, t; }" : "=r"(a) : "l"(p));
    return a;
}
__device__ __forceinline__ void cp16s(uint32_t dst, const void* src) {
    asm volatile("cp.async.cg.shared.global [%0], [%1], 16;" :: "r"(dst), "l"(src));
}
__device__ __forceinline__ void ldmx4(uint32_t* r, uint32_t addr) {
    asm volatile("ldmatrix.sync.aligned.m8n8.x4.shared.b16 {%0,%1,%2,%3}, [%4];"
                 : "=r"(r[0]), "=r"(r[1]), "=r"(r[2]), "=r"(r[3]) : "r"(addr));
}
__device__ __forceinline__ void mma16816(float* c, const uint32_t* a, const uint32_t* b) {
    asm volatile(
        "mma.sync.aligned.m16n8k16.row.col.f32.f16.f16.f32 "
        "{%0,%1,%2,%3}, {%4,%5,%6,%7}, {%8,%9}, {%0,%1,%2,%3};"
        : "+f"(c[0]), "+f"(c[1]), "+f"(c[2]), "+f"(c[3])
        : "r"(a[0]), "r"(a[1]), "r"(a[2]), "r"(a[3]), "r"(b[0]), "r"(b[1]));
}
__device__ __forceinline__ float silu_f(float x) { return x / (1.0f + __expf(-x)); }

// ---------------- small kernels ----------------------------------------------
__global__ void detect_kernel(const unsigned int* __restrict__ m) {
    int i = blockIdx.x * blockDim.x + threadIdx.x;   // 16384 threads = 64KB, in-bounds either way
    if (i == 0) { g_count[0] = 0; g_count[1] = 0; }
    unsigned v = m[i];
    if (v != 0u && v != 1u && v != 0x3F800000u) g_word_mode = 0;
}
__global__ void route_gather(const void* __restrict__ masks, const float* __restrict__ x) {
    int t = blockIdx.x;
    __shared__ int s_slot;
    if (threadIdx.x == 0) {
        bool m0;
        if (g_word_mode) m0 = ((const unsigned int*)masks)[t] != 0u;
        else             m0 = ((const unsigned char*)masks)[t] != 0;
        int e = m0 ? 0 : 1;                    // modality 0 wins on overlap
        int s = atomicAdd(&g_count[e], 1);
        int slot = e * N_TOK + s;
        g_slot[t] = slot;
        s_slot = slot;
    }
    __syncthreads();
    int slot = s_slot;
    float4 v = ((const float4*)(x + (size_t)t * DIMX))[threadIdx.x];
    __half2 h0 = __floats2half2_rn(v.x, v.y);
    __half2 h1 = __floats2half2_rn(v.z, v.w);
    ((uint2*)(g_xh + (size_t)slot * DIMX))[threadIdx.x] =
        make_uint2(*(uint32_t*)&h0, *(uint32_t*)&h1);
}
__global__ void cvtw_all(const float4* __restrict__ w1, const float4* __restrict__ w3,
                         const float4* __restrict__ w2,
                         uint2* __restrict__ d1, uint2* __restrict__ d3,
                         uint2* __restrict__ d2, int n4) {
    int stride = gridDim.x * blockDim.x;
    for (int i = blockIdx.x * blockDim.x + threadIdx.x; i < 3 * n4; i += stride) {
        const float4* s; uint2* d; int j;
        if (i < n4)          { s = w1; d = d1; j = i; }
        else if (i < 2 * n4) { s = w3; d = d3; j = i - n4; }
        else                 { s = w2; d = d2; j = i - 2 * n4; }
        float4 v = s[j];
        __half2 h0 = __floats2half2_rn(v.x, v.y);
        __half2 h1 = __floats2half2_rn(v.z, v.w);
        d[j] = make_uint2(*(uint32_t*)&h0, *(uint32_t*)&h1);
    }
}

// ---------------- fp16 tensor-core GEMM, 512 threads / 32-reg acc -------------
// CTA tile 128x128, 16 warps: wr = wid&3 over M (32 rows), wc = wid>>2 over N.
// Warp tile 32 rows x 32 cols -> acc 32 regs/thread -> 2 CTAs/SM = 32 warps/SM.
// DUAL : B = [w1 (64 rows) | w3 (64 rows)]; warp covers 16 w1-cols + 16 w3-cols;
//        epilogue silu(d1)*d3 -> fp16 C.   NTILE = 64.
// !DUAL: B = 128-row weight tile; warp covers 32 cols; fp16 C.  NTILE = 128.
// Pipeline: 3 stages x BK=64, ONE __syncthreads per k-tile; the 4 prefetch
// cp.asyncs are interleaved into kk0/kk1 to keep MIO free right after the barrier.
template <bool DUAL, int K, int NC, int NTILE>
__global__ void __launch_bounds__(512, 2)
gemm_fp16(const __half* __restrict__ A,
          const __half* __restrict__ W1,
          const __half* __restrict__ W3,
          void* __restrict__ Cout)
{
    extern __shared__ char dyn[];
    const int tid = threadIdx.x;
    const int wid = tid >> 5;
    const int l   = tid & 31;
    const int r0  = blockIdx.y * 128;
    const int e   = r0 >> 15;
    if ((r0 & (N_TOK - 1)) >= g_count[e]) return;
    const int cb  = blockIdx.x * NTILE;

    const uint32_t smem = smem_u32(dyn);
    const __half* W1e = W1 + (size_t)e * NC * K;
    const __half* W3e = DUAL ? (W3 + (size_t)e * NC * K) : W1e;

    // ---- compact loader: 4 chunks/thread (A rows tr,tr+64; B rows tr,tr+64) --
    const int tr = tid >> 3, tc = tid & 7;            // tr in 0..63
    const __half* aSrc  = A + (size_t)(r0 + tr) * K + tc * 8;
    const __half* b1Src = W1e + (size_t)(cb + tr) * K + tc * 8;          // B rows 0-63
    const __half* b3Src = DUAL ? (W3e + (size_t)(cb + tr) * K + tc * 8)  // B rows 64-127
                               : (W1e + (size_t)(cb + 64 + tr) * K + tc * 8);
    const uint32_t offA = tr * ROWPITCH + tc * 16;
    const uint32_t offB = A_BYTES + offA;

    // ---- ldmatrix lane offsets ----
    const int wr = wid & 3, wc = wid >> 2;            // wc in 0..3
    uint32_t a_off[2];
#pragma unroll
    for (int mi = 0; mi < 2; mi++)
        a_off[mi] = (wr * 32 + mi * 16 + (l & 15)) * ROWPITCH + (l >> 4) * 16;
    // bx = first 16-col group, by = second
    const uint32_t bgrp = (l & 7) + ((l >> 4) << 3);
    uint32_t bx_off, by_off;
    if (DUAL) {
        bx_off = A_BYTES + (wc * 16 + bgrp) * ROWPITCH + ((l >> 3) & 1) * 16;
        by_off = bx_off + 64 * ROWPITCH;              // matching w3 cols
    } else {
        bx_off = A_BYTES + (wc * 32 + bgrp) * ROWPITCH + ((l >> 3) & 1) * 16;
        by_off = bx_off + 16 * ROWPITCH;              // cols +16..+31
    }

    float acc[2][4][4];                               // 32 regs
#pragma unroll
    for (int mi = 0; mi < 2; mi++)
#pragma unroll
        for (int ni = 0; ni < 4; ni++)
#pragma unroll
            for (int q = 0; q < 4; q++) acc[mi][ni][q] = 0.f;

    const int KT = K / BK;
    // prologue: fill STAGES-1 stages
#pragma unroll
    for (int s = 0; s < STAGES - 1; s++) {
        const uint32_t sb = smem + s * STAGE_BYTES;
        const int k0 = s * BK;
        cp16s(sb + offA,                  aSrc + k0);
        cp16s(sb + offA + 64 * ROWPITCH,  aSrc + (size_t)64 * K + k0);
        cp16s(sb + offB,                  b1Src + k0);
        cp16s(sb + offB + 64 * ROWPITCH,  b3Src + k0);
        asm volatile("cp.async.commit_group;");
    }

    for (int kt = 0; kt < KT; kt++) {
        asm volatile("cp.async.wait_group %0;" :: "n"(STAGES - 2));
        __syncthreads();

        const bool pf = (kt + STAGES - 1 < KT);
        const uint32_t dst = smem + ((kt + STAGES - 1) % STAGES) * STAGE_BYTES;
        const int k0 = (kt + STAGES - 1) * BK;

        const uint32_t st = smem + (kt % STAGES) * STAGE_BYTES;
#pragma unroll
        for (int kk = 0; kk < 4; kk++) {
            uint32_t a[2][4], bx[4], by[4];
            ldmx4(a[0], st + a_off[0] + kk * 32);
            ldmx4(a[1], st + a_off[1] + kk * 32);
            ldmx4(bx,   st + bx_off   + kk * 32);
            ldmx4(by,   st + by_off   + kk * 32);

            // interleaved prefetch: 2 cp.async after kk0's LDSMs, 2 after kk1's
            if (kk == 0 && pf) {
                cp16s(dst + offA,                 aSrc + k0);
                cp16s(dst + offA + 64 * ROWPITCH, aSrc + (size_t)64 * K + k0);
            } else if (kk == 1) {
                if (pf) {
                    cp16s(dst + offB,                 b1Src + k0);
                    cp16s(dst + offB + 64 * ROWPITCH, b3Src + k0);
                }
                asm volatile("cp.async.commit_group;");   // uniform group count
            }

            // half-round 1: acc[.][0..1] with bx
#pragma unroll
            for (int ni = 0; ni < 2; ni++) {
                const uint32_t* f = &bx[ni * 2];
                mma16816(acc[0][ni], a[0], f);
                mma16816(acc[1][ni], a[1], f);
            }
            // half-round 2: acc[.][2..3] with by
#pragma unroll
            for (int ni = 0; ni < 2; ni++) {
                const uint32_t* f = &by[ni * 2];
                mma16816(acc[0][ni + 2], a[0], f);
                mma16816(acc[1][ni + 2], a[1], f);
            }
        }
    }

    // ---- epilogue (fp16) ----
    const int tgrp = l >> 2, tq = l & 3;
    __half* Ch = (__half*)Cout;
    if (DUAL) {
        // acc[.][0..1] = w1 cols (wc*16 + ni*8), acc[.][2..3] = matching w3 cols
#pragma unroll
        for (int mi = 0; mi < 2; mi++) {
            int row0 = r0 + wr * 32 + mi * 16 + tgrp;
#pragma unroll
            for (int ni = 0; ni < 2; ni++) {
                int col = cb + wc * 16 + ni * 8 + 2 * tq;
                float v0 = silu_f(acc[mi][ni][0]) * acc[mi][ni + 2][0];
                float v1 = silu_f(acc[mi][ni][1]) * acc[mi][ni + 2][1];
                float v2 = silu_f(acc[mi][ni][2]) * acc[mi][ni + 2][2];
                float v3 = silu_f(acc[mi][ni][3]) * acc[mi][ni + 2][3];
                *(__half2*)(Ch + (size_t)row0 * NC + col)       = __floats2half2_rn(v0, v1);
                *(__half2*)(Ch + (size_t)(row0 + 8) * NC + col) = __floats2half2_rn(v2, v3);
            }
        }
    } else {
        // acc[.][ni] = cols wc*32 + ni*8 (bx: 0,8; by: 16,24)
#pragma unroll
        for (int mi = 0; mi < 2; mi++) {
            int row0 = r0 + wr * 32 + mi * 16 + tgrp;
#pragma unroll
            for (int ni = 0; ni < 4; ni++) {
                int col = cb + wc * 32 + ni * 8 + 2 * tq;
                *(__half2*)(Ch + (size_t)row0 * NC + col) =
                    __floats2half2_rn(acc[mi][ni][0], acc[mi][ni][1]);
                *(__half2*)(Ch + (size_t)(row0 + 8) * NC + col) =
                    __floats2half2_rn(acc[mi][ni][2], acc[mi][ni][3]);
            }
        }
    }
}

// ---------------- RMSNorm + scale + scatter (fp16 in, fp32 out) ---------------
__global__ void rms_scatter(const __half* __restrict__ o,
                            const float* __restrict__ norm_w,
                            float* __restrict__ out)
{
    int t = blockIdx.x;
    int tid = threadIdx.x;
    if (t == 0 && tid == 0) g_word_mode = 1;   // re-arm for next call's detect
    int slot = g_slot[t];
    int e = slot >> 15;

    uint4 d = ((const uint4*)(o + (size_t)slot * DIMX))[tid];
    float2 f0 = __half22float2(*(__half2*)&d.x);
    float2 f1 = __half22float2(*(__half2*)&d.y);
    float2 f2 = __half22float2(*(__half2*)&d.z);
    float2 f3 = __half22float2(*(__half2*)&d.w);
    float ss = f0.x*f0.x + f0.y*f0.y + f1.x*f1.x + f1.y*f1.y
             + f2.x*f2.x + f2.y*f2.y + f3.x*f3.x + f3.y*f3.y;
#pragma unroll
    for (int ofs = 16; ofs; ofs >>= 1) ss += __shfl_xor_sync(0xffffffffu, ss, ofs);
    __shared__ float wss[4];
    if ((tid & 31) == 0) wss[tid >> 5] = ss;
    __syncthreads();
    float r = rsqrtf((wss[0] + wss[1] + wss[2] + wss[3]) * (1.0f / DIMX) + 1e-5f);

    const float4* g = (const float4*)(norm_w + (size_t)e * DIMX);
    float4 g0 = g[2 * tid], g1 = g[2 * tid + 1];
    float4* dst = (float4*)(out + (size_t)t * DIMX);
    dst[2 * tid]     = make_float4(f0.x*r*g0.x, f0.y*r*g0.y, f1.x*r*g0.z, f1.y*r*g0.w);
    dst[2 * tid + 1] = make_float4(f2.x*r*g1.x, f2.y*r*g1.y, f3.x*r*g1.z, f3.y*r*g1.w);
}

// ---------------- launcher ----------------------------------------------------
extern "C" void kernel_launch(void* const* d_in, const int* in_sizes, int n_in,
                              void* d_out, int out_size)
{
    const float* x     = (const float*)d_in[0];
    const void*  masks = d_in[1];
    const float* w1    = (const float*)d_in[2];
    const float* w3    = (const float*)d_in[3];
    const float* w2    = (const float*)d_in[4];
    const float* nw    = (const float*)d_in[5];
    float* out = (float*)d_out;

    cudaFuncSetAttribute(gemm_fp16<true,  DIMX, HID,  64>,
                         cudaFuncAttributeMaxDynamicSharedMemorySize, DYN_SMEM);
    cudaFuncSetAttribute(gemm_fp16<false, HID,  DIMX, 128>,
                         cudaFuncAttributeMaxDynamicSharedMemorySize, DYN_SMEM);

    void *xh, *hp, *op, *w1h, *w3h, *w2h;
    cudaGetSymbolAddress(&xh,  g_xh);
    cudaGetSymbolAddress(&hp,  g_h);
    cudaGetSymbolAddress(&op,  g_o);
    cudaGetSymbolAddress(&w1h, g_w1h);
    cudaGetSymbolAddress(&w3h, g_w3h);
    cudaGetSymbolAddress(&w2h, g_w2h);

    detect_kernel<<<64, 256>>>((const unsigned int*)masks);            // 0
    route_gather<<<N_TOK, 256>>>(masks, x);                            // 1

    const int n4 = 2 * HID * DIMX / 4;
    cvtw_all<<<1024, 256>>>((const float4*)w1, (const float4*)w3, (const float4*)w2,
                            (uint2*)w1h, (uint2*)w3h, (uint2*)w2h, n4);        // 2

    // GEMM1: [2N,1024] x w1/w3 -> fused SwiGLU -> g_h [2N, HID] fp16          // 3
    gemm_fp16<true, DIMX, HID, 64><<<dim3(HID / 64, 2 * N_TOK / 128), 512, DYN_SMEM>>>(
        (const __half*)xh, (const __half*)w1h, (const __half*)w3h, hp);
    // GEMM2: [2N,2816] x w2 -> g_o [2N, DIM] fp16                             // 4
    gemm_fp16<false, HID, DIMX, 128><<<dim3(DIMX / 128, 2 * N_TOK / 128), 512, DYN_SMEM>>>(
        (const __half*)hp, (const __half*)w2h, (const __half*)w2h, op);

    rms_scatter<<<N_TOK, 128>>>((const __half*)op, nw, out);                   // 5
}